// round 12
// baseline (speedup 1.0000x reference)
#include <cuda_runtime.h>
#include <cuda_bf16.h>
#include <float.h>
#include <stdint.h>

// ---------------- problem constants ----------------
#define BQ     64
#define HID    768
#define KTOP   5
#define TILE_N 128              // evidence rows per CTA
#define CHK    64               // K per SMEM chunk (2 k32 steps)
#define NCH    (HID / CHK)      // 12
#define NBLK_MAX 3907
#define NCAND  16
#define DSTR   132              // Ds[q][m] stride (floats)

#define A_STR  80               // bytes per int8 row (64 data + 16 pad)
#define A_BUF  (TILE_N * A_STR)     // 10240
#define B_BUF  (BQ * A_STR)         // 5120
#define B_BASE (2 * A_BUF)          // 20480
// union: buffers (30720 B) / Ds (33792 B) -> static 33792
#define SM_BYTES 33792

#define SCALE_E 31.75f          // 127/4  (evidence, sat at 4 sigma)
#define SCALE_Q 768.0f          // normalized queries (|elem| < 0.165 sat)

// ---------------- device scratch ----------------
__device__ float g_qn[BQ * HID];                       // normalized queries fp32
__device__ __align__(16) signed char g_qi8[BQ * HID];  // normalized queries int8
__device__ float g_pscore[BQ * NBLK_MAX * KTOP];
__device__ int   g_pidx[BQ * NBLK_MAX * KTOP];
__device__ int   g_cand[BQ * NCAND];

// ---------------- helpers ----------------
__device__ __forceinline__ uint32_t smem_u32(const void* p) {
    uint32_t a;
    asm("{ .reg .u64 t; cvta.to.shared.u64 t, %1; cvt.u32.u64 %0, t; }" : "=r"(a) : "l"(p));
    return a;
}
__device__ __forceinline__ void ldsm_x4(uint32_t a, uint32_t r[4]) {
    asm volatile("ldmatrix.sync.aligned.m8n8.x4.shared.b16 {%0,%1,%2,%3}, [%4];"
                 : "=r"(r[0]), "=r"(r[1]), "=r"(r[2]), "=r"(r[3]) : "r"(a));
}
__device__ __forceinline__ void imma(int c[4], const uint32_t a[4], const uint32_t b[2]) {
    asm volatile("mma.sync.aligned.m16n8k32.row.col.s32.s8.s8.s32 "
        "{%0,%1,%2,%3}, {%4,%5,%6,%7}, {%8,%9}, {%0,%1,%2,%3};"
        : "+r"(c[0]), "+r"(c[1]), "+r"(c[2]), "+r"(c[3])
        : "r"(a[0]), "r"(a[1]), "r"(a[2]), "r"(a[3]), "r"(b[0]), "r"(b[1]));
}
// quantize float4 -> 4 saturated int8 packed little-endian [x,y,z,w]
__device__ __forceinline__ uint32_t quant4(float4 v) {
    int y0 = __float2int_rn(v.x * SCALE_E);
    int y1 = __float2int_rn(v.y * SCALE_E);
    int y2 = __float2int_rn(v.z * SCALE_E);
    int y3 = __float2int_rn(v.w * SCALE_E);
    uint32_t t, d;
    asm("cvt.pack.sat.s8.s32.b32 %0, %1, %2, %3;" : "=r"(t) : "r"(y3), "r"(y2), "r"(0));
    asm("cvt.pack.sat.s8.s32.b32 %0, %1, %2, %3;" : "=r"(d) : "r"(y1), "r"(y0), "r"(t));
    return d;
}
__device__ __forceinline__ void cpa16(uint32_t dst, const void* src) {
    asm volatile("cp.async.cg.shared.global [%0], [%1], 16;" :: "r"(dst), "l"(src) : "memory");
}
#define CP_COMMIT() asm volatile("cp.async.commit_group;" ::: "memory")
#define CP_WAIT0()  asm volatile("cp.async.wait_group 0;" ::: "memory")

// ---------------------------------------------------------------------------
// K1: normalize queries -> fp32 (rescore) + int8 (GEMM B)
// ---------------------------------------------------------------------------
__global__ void qnorm_kernel(const float* __restrict__ qe) {
    __shared__ float red[8];
    int q = blockIdx.x, tid = threadIdx.x;
    float v0 = qe[q * HID + tid];
    float v1 = qe[q * HID + tid + 256];
    float v2 = qe[q * HID + tid + 512];
    float ss = v0 * v0 + v1 * v1 + v2 * v2;
    #pragma unroll
    for (int o = 16; o; o >>= 1) ss += __shfl_xor_sync(0xffffffffu, ss, o);
    if ((tid & 31) == 0) red[tid >> 5] = ss;
    __syncthreads();
    float tot = 0.f;
    #pragma unroll
    for (int i = 0; i < 8; i++) tot += red[i];
    float r = 1.f / fmaxf(sqrtf(tot), 1e-12f);
    #pragma unroll
    for (int part = 0; part < 3; part++) {
        int k = tid + part * 256;
        float val = (part == 0 ? v0 : (part == 1 ? v1 : v2)) * r;
        g_qn[q * HID + k] = val;
        int y = __float2int_rn(val * SCALE_Q);
        y = max(-127, min(127, y));
        g_qi8[q * HID + k] = (signed char)y;
    }
}

// ---------------------------------------------------------------------------
// K2: s8 IMMA GEMM (m16n8k32), coalesced A LDG, cp.async B, fused norms+top5
// ---------------------------------------------------------------------------
__global__ __launch_bounds__(256)
void sim_kernel(const float* __restrict__ ev, int N) {
    __shared__ __align__(16) unsigned char sm[SM_BYTES];
    __shared__ float s_rnorm[TILE_N];

    int tid = threadIdx.x, w = tid >> 5, lane = tid & 31;
    int n0 = blockIdx.x * TILE_N;
    uint32_t smb = smem_u32(sm);

    // A LDG mapping: slot = tid + 256*i -> row = (tid>>4)+16i, col4 = tid&15
    int rbase = tid >> 4, col4 = tid & 15;
    // B cp.async mapping: qrow = tid>>2 (0..63), c16 = tid&3
    int q0 = tid >> 2, c16 = tid & 3;

    float4 av[8];
    float  nsq[8];
    #pragma unroll
    for (int i = 0; i < 8; i++) nsq[i] = 0.f;
    int acc[8][4];
    #pragma unroll
    for (int t = 0; t < 8; t++)
        #pragma unroll
        for (int j = 0; j < 4; j++) acc[t][j] = 0;

    // ldmatrix invariant addresses (stride 80: rows*80 mod 128 hits 8 banks)
    uint32_t aAddrBase = smb + (uint32_t)(16 * w + (lane & 15)) * A_STR
                             + (uint32_t)(lane >> 4) * 16;
    uint32_t bAddrBase = smb + B_BASE
                       + (uint32_t)((lane & 7) + ((lane >> 4) << 3)) * A_STR
                       + (uint32_t)((lane >> 3) & 1) * 16;

    // ---- prologue: chunk 0 ----
    {
        cpa16(smb + B_BASE + (uint32_t)q0 * A_STR + c16 * 16,
              (const char*)g_qi8 + (size_t)q0 * HID + c16 * 16);
        CP_COMMIT();
        #pragma unroll
        for (int i = 0; i < 8; i++) {
            int r = rbase + 16 * i;
            av[i] = make_float4(0.f, 0.f, 0.f, 0.f);
            if (n0 + r < N)
                av[i] = *(const float4*)&ev[(size_t)(n0 + r) * HID + col4 * 4];
        }
        #pragma unroll
        for (int i = 0; i < 8; i++) {
            float4 v = av[i];
            nsq[i] += v.x * v.x + v.y * v.y + v.z * v.z + v.w * v.w;
            *(uint32_t*)(sm + (rbase + 16 * i) * A_STR + col4 * 4) = quant4(v);
        }
        CP_WAIT0();
    }
    __syncthreads();

    // ---- main loop ----
    for (int c = 0; c < NCH; ++c) {
        int buf = c & 1, nxt = buf ^ 1;
        bool more = (c + 1 < NCH);
        if (more) {
            int k0 = (c + 1) * CHK;
            cpa16(smb + B_BASE + (uint32_t)nxt * B_BUF + (uint32_t)q0 * A_STR + c16 * 16,
                  (const char*)g_qi8 + (size_t)q0 * HID + k0 + c16 * 16);
            CP_COMMIT();
            #pragma unroll
            for (int i = 0; i < 8; i++) {
                int r = rbase + 16 * i;
                av[i] = make_float4(0.f, 0.f, 0.f, 0.f);
                if (n0 + r < N)
                    av[i] = *(const float4*)&ev[(size_t)(n0 + r) * HID + k0 + col4 * 4];
            }
        }

        // compute current buffer: 2 k32 steps x 8 n-tiles
        {
            uint32_t ab = aAddrBase + (uint32_t)buf * A_BUF;
            uint32_t bb = bAddrBase + (uint32_t)buf * B_BUF;
            #pragma unroll
            for (int s = 0; s < 2; s++) {
                uint32_t af[4];
                ldsm_x4(ab + s * 32, af);
                #pragma unroll
                for (int tp = 0; tp < 4; tp++) {
                    uint32_t bf[4];
                    ldsm_x4(bb + (uint32_t)tp * (16 * A_STR) + s * 32, bf);
                    imma(acc[2 * tp],     af, bf);
                    imma(acc[2 * tp + 1], af, bf + 2);
                }
            }
        }

        if (more) {   // quantize + store into the buffer compute(c) did NOT read
            unsigned char* Ab = sm + nxt * A_BUF;
            #pragma unroll
            for (int i = 0; i < 8; i++) {
                float4 v = av[i];
                nsq[i] += v.x * v.x + v.y * v.y + v.z * v.z + v.w * v.w;
                *(uint32_t*)(Ab + (rbase + 16 * i) * A_STR + col4 * 4) = quant4(v);
            }
        }
        CP_WAIT0();
        __syncthreads();
    }

    // ---- evidence norms: reduce across the 16 threads sharing each row ----
    #pragma unroll
    for (int i = 0; i < 8; i++) {
        float v = nsq[i];
        v += __shfl_xor_sync(0xffffffffu, v, 1, 16);
        v += __shfl_xor_sync(0xffffffffu, v, 2, 16);
        v += __shfl_xor_sync(0xffffffffu, v, 4, 16);
        v += __shfl_xor_sync(0xffffffffu, v, 8, 16);
        if ((tid & 15) == 0)
            s_rnorm[rbase + 16 * i] = 1.f / fmaxf(sqrtf(v), 1e-12f);
    }
    __syncthreads();

    // ---- stage scaled approx scores Ds[q][m] (smem union) ----
    // score = (float)idot * rnorm; global int scales are per-query constant
    // -> ranking-identical. s32 |idot| < 2^24 so conversion is exact.
    float* Ds = (float*)sm;
    int mlo = 16 * w + (lane >> 2), mhi = mlo + 8;
    float rlo = s_rnorm[mlo], rhi = s_rnorm[mhi];
    bool vlo = (n0 + mlo) < N, vhi = (n0 + mhi) < N;
    #pragma unroll
    for (int t = 0; t < 8; t++) {
        int n = 8 * t + 2 * (lane & 3);
        Ds[n * DSTR + mlo]       = vlo ? (float)acc[t][0] * rlo : -FLT_MAX;
        Ds[(n + 1) * DSTR + mlo] = vlo ? (float)acc[t][1] * rlo : -FLT_MAX;
        Ds[n * DSTR + mhi]       = vhi ? (float)acc[t][2] * rhi : -FLT_MAX;
        Ds[(n + 1) * DSTR + mhi] = vhi ? (float)acc[t][3] * rhi : -FLT_MAX;
    }
    __syncthreads();

    // ---- per-block approx top-5: warp w owns queries 8w..8w+7 ----
    for (int j = 0; j < 8; j++) {
        int q = w * 8 + j;
        float c0 = Ds[q * DSTR + lane];
        float c1 = Ds[q * DSTR + lane + 32];
        float c2 = Ds[q * DSTR + lane + 64];
        float c3 = Ds[q * DSTR + lane + 96];
        int i0 = lane, i1 = lane + 32, i2 = lane + 64, i3 = lane + 96;
        #pragma unroll
        for (int t = 0; t < KTOP; t++) {
            float bs = c0; int bi = i0;
            if (c1 > bs || (c1 == bs && i1 < bi)) { bs = c1; bi = i1; }
            if (c2 > bs || (c2 == bs && i2 < bi)) { bs = c2; bi = i2; }
            if (c3 > bs || (c3 == bs && i3 < bi)) { bs = c3; bi = i3; }
            #pragma unroll
            for (int o = 16; o; o >>= 1) {
                float os = __shfl_xor_sync(0xffffffffu, bs, o);
                int   oi = __shfl_xor_sync(0xffffffffu, bi, o);
                if (os > bs || (os == bs && oi < bi)) { bs = os; bi = oi; }
            }
            if (lane == 0) {
                size_t p = ((size_t)q * gridDim.x + blockIdx.x) * KTOP + t;
                g_pscore[p] = bs;
                g_pidx[p]   = n0 + bi;
            }
            if      (i0 == bi) c0 = -FLT_MAX;
            else if (i1 == bi) c1 = -FLT_MAX;
            else if (i2 == bi) c2 = -FLT_MAX;
            else if (i3 == bi) c3 = -FLT_MAX;
        }
    }
}

// ---------------------------------------------------------------------------
// K3: merge per-block partials -> global top-16 candidates per query
// ---------------------------------------------------------------------------
__device__ __forceinline__ void ins16(float* s, int* id, float sc, int ix) {
    if (!(sc > s[NCAND-1] || (sc == s[NCAND-1] && ix < id[NCAND-1]))) return;
    int j = NCAND - 1;
    while (j > 0 && (sc > s[j-1] || (sc == s[j-1] && ix < id[j-1]))) {
        s[j] = s[j-1]; id[j] = id[j-1]; --j;
    }
    s[j] = sc; id[j] = ix;
}

__global__ void merge_kernel(int nblk) {
    __shared__ float ss[256 * NCAND];
    __shared__ int   si[256 * NCAND];
    int q = blockIdx.x, tid = threadIdx.x;
    int M = nblk * KTOP;

    float s[NCAND]; int id[NCAND];
    #pragma unroll
    for (int j = 0; j < NCAND; j++) { s[j] = -FLT_MAX; id[j] = 0x7fffffff; }
    size_t bse = (size_t)q * nblk * KTOP;
    for (int c = tid; c < M; c += 256)
        ins16(s, id, g_pscore[bse + c], g_pidx[bse + c]);
    #pragma unroll
    for (int j = 0; j < NCAND; j++) { ss[tid*NCAND+j] = s[j]; si[tid*NCAND+j] = id[j]; }
    __syncthreads();

    if (tid < 32) {
        float s2[NCAND]; int i2[NCAND];
        #pragma unroll
        for (int j = 0; j < NCAND; j++) { s2[j] = -FLT_MAX; i2[j] = 0x7fffffff; }
        for (int c = tid; c < 256 * NCAND; c += 32) ins16(s2, i2, ss[c], si[c]);
        __syncwarp();
        #pragma unroll
        for (int j = 0; j < NCAND; j++) { ss[tid*NCAND+j] = s2[j]; si[tid*NCAND+j] = i2[j]; }
        __syncwarp();
        if (tid == 0) {
            float s3[NCAND]; int i3[NCAND];
            #pragma unroll
            for (int j = 0; j < NCAND; j++) { s3[j] = -FLT_MAX; i3[j] = 0x7fffffff; }
            for (int c = 0; c < 32 * NCAND; c++) ins16(s3, i3, ss[c], si[c]);
            #pragma unroll
            for (int j = 0; j < NCAND; j++) g_cand[q * NCAND + j] = i3[j];
        }
    }
}

// ---------------------------------------------------------------------------
// K4: exact fp32 rescore of 16 candidates per query -> final top-5
// ---------------------------------------------------------------------------
__global__ void rescore_kernel(const float* __restrict__ ev,
                               float* __restrict__ out, int out_size) {
    __shared__ float cs[NCAND];
    int q = blockIdx.x, tid = threadIdx.x;
    int w = tid >> 5, lane = tid & 31;

    for (int t = 0; t < 4; t++) {
        int c = w * 4 + t;
        int idx = g_cand[q * NCAND + c];
        const float* e = &ev[(size_t)idx * HID];
        const float* qv = &g_qn[q * HID];
        float dot = 0.f, ssq = 0.f;
        #pragma unroll
        for (int kk = 0; kk < HID / 32; kk++) {
            float x = e[lane + kk * 32];
            dot += x * qv[lane + kk * 32];
            ssq += x * x;
        }
        #pragma unroll
        for (int o = 16; o; o >>= 1) {
            dot += __shfl_xor_sync(0xffffffffu, dot, o);
            ssq += __shfl_xor_sync(0xffffffffu, ssq, o);
        }
        if (lane == 0) cs[c] = dot / fmaxf(sqrtf(ssq), 1e-12f);
    }
    __syncthreads();

    if (w == 0) {
        float sc = (lane < NCAND) ? cs[lane] : -FLT_MAX;
        int   ix = (lane < NCAND) ? g_cand[q * NCAND + lane] : 0x7fffffff;
        #pragma unroll
        for (int t = 0; t < KTOP; t++) {
            float bs = sc; int bi = ix;
            #pragma unroll
            for (int o = 16; o; o >>= 1) {
                float os = __shfl_xor_sync(0xffffffffu, bs, o);
                int   oi = __shfl_xor_sync(0xffffffffu, bi, o);
                if (os > bs || (os == bs && oi < bi)) { bs = os; bi = oi; }
            }
            if (lane == 0) {
                int pi = q * KTOP + t;
                int ps = BQ * KTOP + q * KTOP + t;
                if (pi < out_size) out[pi] = (float)bi;
                if (ps < out_size) out[ps] = bs;
            }
            if (ix == bi) sc = -FLT_MAX;   // winner pops (indices unique)
        }
    }
}

// ---------------------------------------------------------------------------
extern "C" void kernel_launch(void* const* d_in, const int* in_sizes, int n_in,
                              void* d_out, int out_size) {
    (void)n_in;
    const float* qe = (const float*)d_in[0];
    const float* ev = (const float*)d_in[1];
    float* out = (float*)d_out;

    int N = in_sizes[1] / HID;
    int nblk = (N + TILE_N - 1) / TILE_N;
    if (nblk > NBLK_MAX) nblk = NBLK_MAX;

    qnorm_kernel<<<BQ, 256>>>(qe);
    sim_kernel<<<nblk, 256>>>(ev, N);
    merge_kernel<<<BQ, 256>>>(nblk);
    rescore_kernel<<<BQ, 128>>>(ev, out, out_size);
}

// round 14
// speedup vs baseline: 1.4146x; 1.4146x over previous
#include <cuda_runtime.h>
#include <cuda_bf16.h>
#include <float.h>
#include <stdint.h>

// ---------------- problem constants ----------------
#define BQ     64
#define HID    768
#define KTOP   5
#define TILE_N 128              // evidence rows per CTA
#define CHK    64               // K per chunk = 16 k-words
#define NCH    (HID / CHK)      // 12
#define NKW    (HID / 4)        // 192 k-words total
#define NBLK_MAX 3907
#define NCAND  16
#define DSTR   132              // Ds[q][m] stride (floats)

#define AW 132                  // words per k-word row, A tile (128 + 4 pad)
#define BW 68                   // words per k-word row, B tile (64 + 4 pad)
#define A_BUF_W (16 * AW)       // 2112
#define B_BUF_W (16 * BW)       // 1088
#define B_BASE_W (2 * A_BUF_W)  // 4224
// union: buffers 6400 words / Ds 8448 words -> 8448 words = 33792 B
#define SM_WORDS 8448

#define SCALE_E 31.75f          // 127/4  (evidence, sat at 4 sigma)
#define SCALE_Q 768.0f          // normalized queries

// ---------------- device scratch ----------------
__device__ float g_qn[BQ * HID];                        // normalized queries fp32
__device__ __align__(16) uint32_t g_qT[NKW * BQ];       // packed q words [kw][q]
__device__ float g_pscore[BQ * NBLK_MAX * KTOP];
__device__ int   g_pidx[BQ * NBLK_MAX * KTOP];
__device__ int   g_cand[BQ * NCAND];

// ---------------- helpers ----------------
__device__ __forceinline__ uint32_t smem_u32(const void* p) {
    uint32_t a;
    asm("{ .reg .u64 t; cvta.to.shared.u64 t, %1; cvt.u32.u64 %0, t; }" : "=r"(a) : "l"(p));
    return a;
}
// quantize float4 -> 4 saturated int8 packed little-endian [x,y,z,w]
__device__ __forceinline__ uint32_t quant4(float4 v) {
    int y0 = __float2int_rn(v.x * SCALE_E);
    int y1 = __float2int_rn(v.y * SCALE_E);
    int y2 = __float2int_rn(v.z * SCALE_E);
    int y3 = __float2int_rn(v.w * SCALE_E);
    uint32_t t, d;
    asm("cvt.pack.sat.s8.s32.b32 %0, %1, %2, %3;" : "=r"(t) : "r"(y3), "r"(y2), "r"(0));
    asm("cvt.pack.sat.s8.s32.b32 %0, %1, %2, %3;" : "=r"(d) : "r"(y1), "r"(y0), "r"(t));
    return d;
}
__device__ __forceinline__ void cpa16(uint32_t dst, const void* src) {
    asm volatile("cp.async.cg.shared.global [%0], [%1], 16;" :: "r"(dst), "l"(src) : "memory");
}
#define CP_COMMIT() asm volatile("cp.async.commit_group;" ::: "memory")
#define CP_WAIT0()  asm volatile("cp.async.wait_group 0;" ::: "memory")

// ---------------------------------------------------------------------------
// K1: normalize queries -> fp32 (rescore) + packed int8 words [kw][q]
// ---------------------------------------------------------------------------
__global__ void qnorm_kernel(const float* __restrict__ qe) {
    __shared__ float red[8];
    __shared__ signed char s8[HID];
    int q = blockIdx.x, tid = threadIdx.x;
    float v0 = qe[q * HID + tid];
    float v1 = qe[q * HID + tid + 256];
    float v2 = qe[q * HID + tid + 512];
    float ss = v0 * v0 + v1 * v1 + v2 * v2;
    #pragma unroll
    for (int o = 16; o; o >>= 1) ss += __shfl_xor_sync(0xffffffffu, ss, o);
    if ((tid & 31) == 0) red[tid >> 5] = ss;
    __syncthreads();
    float tot = 0.f;
    #pragma unroll
    for (int i = 0; i < 8; i++) tot += red[i];
    float r = 1.f / fmaxf(sqrtf(tot), 1e-12f);
    #pragma unroll
    for (int part = 0; part < 3; part++) {
        int k = tid + part * 256;
        float val = (part == 0 ? v0 : (part == 1 ? v1 : v2)) * r;
        g_qn[q * HID + k] = val;
        int y = __float2int_rn(val * SCALE_Q);
        y = max(-127, min(127, y));
        s8[k] = (signed char)y;
    }
    __syncthreads();
    if (tid < NKW) {
        int kw = tid;
        uint32_t wv = ((uint32_t)(unsigned char)s8[4 * kw])
                    | ((uint32_t)(unsigned char)s8[4 * kw + 1] << 8)
                    | ((uint32_t)(unsigned char)s8[4 * kw + 2] << 16)
                    | ((uint32_t)(unsigned char)s8[4 * kw + 3] << 24);
        g_qT[kw * BQ + q] = wv;
    }
}

// ---------------------------------------------------------------------------
// K2: int8 dp4a GEMM, [kw][row] layouts, double-buffered, fused norms + top5
//   256 threads. Compute: te=tid>>3 owns ev rows te*4..+3; tq=tid&7 owns
//   queries {4tq..4tq+3} and {32+4tq..32+4tq+3} (bank-conflict-free B reads).
// ---------------------------------------------------------------------------
__global__ __launch_bounds__(256)
void sim_kernel(const float* __restrict__ ev, int N) {
    __shared__ __align__(16) uint32_t sm[SM_WORDS];
    __shared__ float s_rnorm[TILE_N];

    int tid = threadIdx.x, w = tid >> 5, lane = tid & 31;
    int n0 = blockIdx.x * TILE_N;
    uint32_t smb = smem_u32(sm);

    // A loader: slot = tid + 256*i -> row = (tid>>4)+16i, c16 = tid&15 (kw in chunk)
    int rbase = tid >> 4, c16 = tid & 15;
    // compute mapping
    int te = tid >> 3, tq = tid & 7;

    float4 av[8];
    float  nsq[8];
    #pragma unroll
    for (int i = 0; i < 8; i++) nsq[i] = 0.f;
    int acc[4][8];
    #pragma unroll
    for (int e = 0; e < 4; e++)
        #pragma unroll
        for (int qd = 0; qd < 8; qd++) acc[e][qd] = 0;

    // ---- prologue: chunk 0 ----
    {
        cpa16(smb + (uint32_t)(B_BASE_W + (tid >> 4) * BW + (tid & 15) * 4) * 4,
              g_qT + tid * 4);
        CP_COMMIT();
        #pragma unroll
        for (int i = 0; i < 8; i++) {
            int r = rbase + 16 * i;
            av[i] = make_float4(0.f, 0.f, 0.f, 0.f);
            if (n0 + r < N)
                av[i] = *(const float4*)&ev[(size_t)(n0 + r) * HID + c16 * 4];
        }
        #pragma unroll
        for (int i = 0; i < 8; i++) {
            float4 v = av[i];
            nsq[i] += v.x * v.x + v.y * v.y + v.z * v.z + v.w * v.w;
            sm[c16 * AW + rbase + 16 * i] = quant4(v);
        }
        CP_WAIT0();
    }
    __syncthreads();

    // ---- main loop ----
    for (int c = 0; c < NCH; ++c) {
        int buf = c & 1, nxt = buf ^ 1;
        bool more = (c + 1 < NCH);
        if (more) {
            int k0 = (c + 1) * CHK;
            cpa16(smb + (uint32_t)(B_BASE_W + nxt * B_BUF_W
                         + (tid >> 4) * BW + (tid & 15) * 4) * 4,
                  g_qT + (c + 1) * (16 * BQ) + tid * 4);
            CP_COMMIT();
            #pragma unroll
            for (int i = 0; i < 8; i++) {
                int r = rbase + 16 * i;
                av[i] = make_float4(0.f, 0.f, 0.f, 0.f);
                if (n0 + r < N)
                    av[i] = *(const float4*)&ev[(size_t)(n0 + r) * HID + k0 + c16 * 4];
            }
        }

        // compute current buffer: 16 k-words, 32 dp4a each.
        // B reads: words 4tq..4tq+3 (phase covers words 0..31 -> all banks)
        //      and 32+4tq..+3 (words 32..63 -> all banks): conflict-free.
        {
            const uint32_t* Ab = sm + buf * A_BUF_W;
            const uint32_t* Bb = sm + B_BASE_W + buf * B_BUF_W;
            #pragma unroll
            for (int kw = 0; kw < 16; kw++) {
                uint4 a4 = *(const uint4*)&Ab[kw * AW + te * 4];
                uint4 bA = *(const uint4*)&Bb[kw * BW + tq * 4];
                uint4 bB = *(const uint4*)&Bb[kw * BW + 32 + tq * 4];
                uint32_t ar[4] = {a4.x, a4.y, a4.z, a4.w};
                uint32_t br[8] = {bA.x, bA.y, bA.z, bA.w, bB.x, bB.y, bB.z, bB.w};
                #pragma unroll
                for (int e = 0; e < 4; e++)
                    #pragma unroll
                    for (int qd = 0; qd < 8; qd++)
                        acc[e][qd] = __dp4a((int)ar[e], (int)br[qd], acc[e][qd]);
            }
        }

        if (more) {   // quantize + store into the buffer compute(c) did NOT read
            uint32_t* Ab = sm + nxt * A_BUF_W;
            #pragma unroll
            for (int i = 0; i < 8; i++) {
                float4 v = av[i];
                nsq[i] += v.x * v.x + v.y * v.y + v.z * v.z + v.w * v.w;
                Ab[c16 * AW + rbase + 16 * i] = quant4(v);
            }
        }
        CP_WAIT0();
        __syncthreads();
    }

    // ---- evidence norms: reduce across the 16 threads sharing each row ----
    #pragma unroll
    for (int i = 0; i < 8; i++) {
        float v = nsq[i];
        v += __shfl_xor_sync(0xffffffffu, v, 1, 16);
        v += __shfl_xor_sync(0xffffffffu, v, 2, 16);
        v += __shfl_xor_sync(0xffffffffu, v, 4, 16);
        v += __shfl_xor_sync(0xffffffffu, v, 8, 16);
        if ((tid & 15) == 0)
            s_rnorm[rbase + 16 * i] = 1.f / fmaxf(sqrtf(v), 1e-12f);
    }
    __syncthreads();

    // ---- stage scaled approx scores Ds[q][m] (smem union) ----
    // q(qd): qd<4 -> 4tq+qd ; qd>=4 -> 32+4tq+(qd-4)
    float* Ds = (float*)sm;
    #pragma unroll
    for (int e = 0; e < 4; e++) {
        int m = te * 4 + e;
        float rn = s_rnorm[m];
        bool vld = (n0 + m) < N;
        #pragma unroll
        for (int qd = 0; qd < 8; qd++) {
            int q = (qd < 4) ? (tq * 4 + qd) : (32 + tq * 4 + (qd - 4));
            Ds[q * DSTR + m] = vld ? (float)acc[e][qd] * rn : -FLT_MAX;
        }
    }
    __syncthreads();

    // ---- per-block approx top-5: warp w owns queries 8w..8w+7 ----
    for (int j = 0; j < 8; j++) {
        int q = w * 8 + j;
        float c0 = Ds[q * DSTR + lane];
        float c1 = Ds[q * DSTR + lane + 32];
        float c2 = Ds[q * DSTR + lane + 64];
        float c3 = Ds[q * DSTR + lane + 96];
        int i0 = lane, i1 = lane + 32, i2 = lane + 64, i3 = lane + 96;
        #pragma unroll
        for (int t = 0; t < KTOP; t++) {
            float bs = c0; int bi = i0;
            if (c1 > bs || (c1 == bs && i1 < bi)) { bs = c1; bi = i1; }
            if (c2 > bs || (c2 == bs && i2 < bi)) { bs = c2; bi = i2; }
            if (c3 > bs || (c3 == bs && i3 < bi)) { bs = c3; bi = i3; }
            #pragma unroll
            for (int o = 16; o; o >>= 1) {
                float os = __shfl_xor_sync(0xffffffffu, bs, o);
                int   oi = __shfl_xor_sync(0xffffffffu, bi, o);
                if (os > bs || (os == bs && oi < bi)) { bs = os; bi = oi; }
            }
            if (lane == 0) {
                size_t p = ((size_t)q * gridDim.x + blockIdx.x) * KTOP + t;
                g_pscore[p] = bs;
                g_pidx[p]   = n0 + bi;
            }
            if      (i0 == bi) c0 = -FLT_MAX;
            else if (i1 == bi) c1 = -FLT_MAX;
            else if (i2 == bi) c2 = -FLT_MAX;
            else if (i3 == bi) c3 = -FLT_MAX;
        }
    }
}

// ---------------------------------------------------------------------------
// K3: merge per-block partials -> global top-16 candidates per query
// ---------------------------------------------------------------------------
__device__ __forceinline__ void ins16(float* s, int* id, float sc, int ix) {
    if (!(sc > s[NCAND-1] || (sc == s[NCAND-1] && ix < id[NCAND-1]))) return;
    int j = NCAND - 1;
    while (j > 0 && (sc > s[j-1] || (sc == s[j-1] && ix < id[j-1]))) {
        s[j] = s[j-1]; id[j] = id[j-1]; --j;
    }
    s[j] = sc; id[j] = ix;
}

__global__ void merge_kernel(int nblk) {
    __shared__ float ss[256 * NCAND];
    __shared__ int   si[256 * NCAND];
    int q = blockIdx.x, tid = threadIdx.x;
    int M = nblk * KTOP;

    float s[NCAND]; int id[NCAND];
    #pragma unroll
    for (int j = 0; j < NCAND; j++) { s[j] = -FLT_MAX; id[j] = 0x7fffffff; }
    size_t bse = (size_t)q * nblk * KTOP;
    for (int c = tid; c < M; c += 256)
        ins16(s, id, g_pscore[bse + c], g_pidx[bse + c]);
    #pragma unroll
    for (int j = 0; j < NCAND; j++) { ss[tid*NCAND+j] = s[j]; si[tid*NCAND+j] = id[j]; }
    __syncthreads();

    if (tid < 32) {
        float s2[NCAND]; int i2[NCAND];
        #pragma unroll
        for (int j = 0; j < NCAND; j++) { s2[j] = -FLT_MAX; i2[j] = 0x7fffffff; }
        for (int c = tid; c < 256 * NCAND; c += 32) ins16(s2, i2, ss[c], si[c]);
        __syncwarp();
        #pragma unroll
        for (int j = 0; j < NCAND; j++) { ss[tid*NCAND+j] = s2[j]; si[tid*NCAND+j] = i2[j]; }
        __syncwarp();
        if (tid == 0) {
            float s3[NCAND]; int i3[NCAND];
            #pragma unroll
            for (int j = 0; j < NCAND; j++) { s3[j] = -FLT_MAX; i3[j] = 0x7fffffff; }
            for (int c = 0; c < 32 * NCAND; c++) ins16(s3, i3, ss[c], si[c]);
            #pragma unroll
            for (int j = 0; j < NCAND; j++) g_cand[q * NCAND + j] = i3[j];
        }
    }
}

// ---------------------------------------------------------------------------
// K4: exact fp32 rescore of 16 candidates per query -> final top-5
// ---------------------------------------------------------------------------
__global__ void rescore_kernel(const float* __restrict__ ev,
                               float* __restrict__ out, int out_size) {
    __shared__ float cs[NCAND];
    int q = blockIdx.x, tid = threadIdx.x;
    int w = tid >> 5, lane = tid & 31;

    for (int t = 0; t < 4; t++) {
        int c = w * 4 + t;
        int idx = g_cand[q * NCAND + c];
        const float* e = &ev[(size_t)idx * HID];
        const float* qv = &g_qn[q * HID];
        float dot = 0.f, ssq = 0.f;
        #pragma unroll
        for (int kk = 0; kk < HID / 32; kk++) {
            float x = e[lane + kk * 32];
            dot += x * qv[lane + kk * 32];
            ssq += x * x;
        }
        #pragma unroll
        for (int o = 16; o; o >>= 1) {
            dot += __shfl_xor_sync(0xffffffffu, dot, o);
            ssq += __shfl_xor_sync(0xffffffffu, ssq, o);
        }
        if (lane == 0) cs[c] = dot / fmaxf(sqrtf(ssq), 1e-12f);
    }
    __syncthreads();

    if (w == 0) {
        float sc = (lane < NCAND) ? cs[lane] : -FLT_MAX;
        int   ix = (lane < NCAND) ? g_cand[q * NCAND + lane] : 0x7fffffff;
        #pragma unroll
        for (int t = 0; t < KTOP; t++) {
            float bs = sc; int bi = ix;
            #pragma unroll
            for (int o = 16; o; o >>= 1) {
                float os = __shfl_xor_sync(0xffffffffu, bs, o);
                int   oi = __shfl_xor_sync(0xffffffffu, bi, o);
                if (os > bs || (os == bs && oi < bi)) { bs = os; bi = oi; }
            }
            if (lane == 0) {
                int pi = q * KTOP + t;
                int ps = BQ * KTOP + q * KTOP + t;
                if (pi < out_size) out[pi] = (float)bi;
                if (ps < out_size) out[ps] = bs;
            }
            if (ix == bi) sc = -FLT_MAX;   // winner pops (indices unique)
        }
    }
}

// ---------------------------------------------------------------------------
extern "C" void kernel_launch(void* const* d_in, const int* in_sizes, int n_in,
                              void* d_out, int out_size) {
    (void)n_in;
    const float* qe = (const float*)d_in[0];
    const float* ev = (const float*)d_in[1];
    float* out = (float*)d_out;

    int N = in_sizes[1] / HID;
    int nblk = (N + TILE_N - 1) / TILE_N;
    if (nblk > NBLK_MAX) nblk = NBLK_MAX;

    qnorm_kernel<<<BQ, 256>>>(qe);
    sim_kernel<<<nblk, 256>>>(ev, N);
    merge_kernel<<<BQ, 256>>>(nblk);
    rescore_kernel<<<BQ, 128>>>(ev, out, out_size);
}